// round 1
// baseline (speedup 1.0000x reference)
#include <cuda_runtime.h>

#define NB      16
#define NFRAMES 1024
#define BINS    513
#define WIN     1024
#define HOP     256
#define OUTLEN  262912          // (1024-1)*256 + 1024
#define HOPS_PER_BLK 16
#define BLK     (HOPS_PER_BLK * HOP)          // 4096 samples per CTA
#define NBLK    ((OUTLEN + BLK - 1) / BLK)    // 65

// One CTA: batch b, output samples [base, base+blkLen).
// Needs frames f with f*HOP <= t < f*HOP+WIN for t in block -> up to 19 frames.
// 256 threads process 2 frames at a time (128 threads per 512-pt complex IFFT).
__global__ void __launch_bounds__(256) istft_kernel(
    const float* __restrict__ re,
    const float* __restrict__ im,
    float* __restrict__ out)
{
    __shared__ float2 tw[1024];        // e^{+2*pi*i*k/1024}
    __shared__ float2 buf[2][2][512];  // [pingpong][half][point]
    __shared__ float  acc[BLK];

    const int tid  = threadIdx.x;
    const int half = tid >> 7;     // which frame of the pair
    const int t    = tid & 127;    // lane within the 128-thread FFT

    const int b      = blockIdx.y;
    const int base   = blockIdx.x * BLK;
    const int blkLen = min(BLK, OUTLEN - base);

    // Twiddle table (also provides Hann window: w[n] = 0.5 - 0.5*tw[n].x)
    for (int k = tid; k < 1024; k += 256) {
        float s, c;
        sincospif(k * (1.0f / 512.0f), &s, &c);  // angle = 2*pi*k/1024
        tw[k] = make_float2(c, s);
    }
    for (int i = tid; i < BLK; i += 256) acc[i] = 0.0f;
    __syncthreads();

    // Frame range overlapping this block (exact: base multiple of HOP)
    const int f_lo = max(0, (base - WIN) / HOP + 1);
    const int f_hi = min(NFRAMES - 1, (base + blkLen - 1) / HOP);

    for (int fp = f_lo; fp <= f_hi; fp += 2) {
        int f = fp + half;
        const bool active = (f <= f_hi);
        if (!active) f = f_hi;  // clamp: redundant compute, skip accumulate

        // ---- Build Z[k] for the half-size complex IFFT (pack trick) ----
        // E[k]  = 0.5*(X[k] + conj(X[512-k]))
        // Od[k] = 0.5*(X[k] - conj(X[512-k]))
        // O[k]  = Od[k] * e^{+2*pi*i*k/1024};  Z = E + i*O
        {
            const float* rp = re + ((size_t)b * NFRAMES + f) * BINS;
            const float* ip = im + ((size_t)b * NFRAMES + f) * BINS;
            float2* z = buf[0][half];
            #pragma unroll
            for (int r = 0; r < 4; r++) {
                int k = t + r * 128;
                float xr = rp[k],        xi = ip[k];
                float yr = rp[512 - k],  yi = ip[512 - k];
                if (k == 0) { xi = 0.0f; yi = 0.0f; }  // irfft ignores Im(DC), Im(Nyquist)
                float Er  = 0.5f * (xr + yr), Ei  = 0.5f * (xi - yi);
                float Odr = 0.5f * (xr - yr), Odi = 0.5f * (xi + yi);
                float2 w = tw[k];
                float Ox = Odr * w.x - Odi * w.y;
                float Oy = Odr * w.y + Odi * w.x;
                z[k] = make_float2(Er - Oy, Ei + Ox);
            }
        }
        __syncthreads();

        // ---- 512-pt inverse FFT: 4 radix-4 Stockham stages + 1 radix-2 ----
        int cur = 0;
        #pragma unroll
        for (int st = 0; st < 4; st++) {
            const int s = 1 << (2 * st);        // 1,4,16,64
            const float2* sp = buf[cur][half];
            float2*       dp = buf[cur ^ 1][half];
            const int ofs = t & ~(s - 1);       // p*s
            float2 a  = sp[t];
            float2 bq = sp[t + 128];
            float2 c  = sp[t + 256];
            float2 d  = sp[t + 384];
            float2 w1 = tw[2 * ofs];            // e^{+2*pi*i*ofs/512}
            float2 w2 = make_float2(w1.x * w1.x - w1.y * w1.y, 2.0f * w1.x * w1.y);
            float2 w3 = make_float2(w2.x * w1.x - w2.y * w1.y, w2.x * w1.y + w2.y * w1.x);
            float2 apc = make_float2(a.x + c.x, a.y + c.y);
            float2 amc = make_float2(a.x - c.x, a.y - c.y);
            float2 bpd = make_float2(bq.x + d.x, bq.y + d.y);
            float2 bmd = make_float2(bq.x - d.x, bq.y - d.y);
            float2 y0 = make_float2(apc.x + bpd.x, apc.y + bpd.y);
            float2 y2 = make_float2(apc.x - bpd.x, apc.y - bpd.y);
            float2 ib = make_float2(-bmd.y, bmd.x);            // +i*(b-d) (inverse)
            float2 y1 = make_float2(amc.x + ib.x, amc.y + ib.y);
            float2 y3 = make_float2(amc.x - ib.x, amc.y - ib.y);
            const int dbase = t + 3 * ofs;
            dp[dbase]         = y0;
            dp[dbase + s]     = make_float2(y1.x * w1.x - y1.y * w1.y, y1.x * w1.y + y1.y * w1.x);
            dp[dbase + 2 * s] = make_float2(y2.x * w2.x - y2.y * w2.y, y2.x * w2.y + y2.y * w2.x);
            dp[dbase + 3 * s] = make_float2(y3.x * w3.x - y3.y * w3.y, y3.x * w3.y + y3.y * w3.x);
            cur ^= 1;
            __syncthreads();
        }
        {   // radix-2 final stage: n=2, s=256, twiddle = 1
            const float2* sp = buf[cur][half];
            float2*       dp = buf[cur ^ 1][half];
            #pragma unroll
            for (int r = 0; r < 2; r++) {
                int tt = t + r * 128;
                float2 a  = sp[tt];
                float2 bq = sp[tt + 256];
                dp[tt]       = make_float2(a.x + bq.x, a.y + bq.y);
                dp[tt + 256] = make_float2(a.x - bq.x, a.y - bq.y);
            }
            cur ^= 1;
            __syncthreads();
        }

        // ---- window * frame, overlap-add into shared accumulator ----
        // z[m] = x[2m] + i*x[2m+1] (unnormalized by 512)
        if (active) {
            const float2* zz = buf[cur][half];
            const int foff = f * HOP - base;
            #pragma unroll
            for (int r = 0; r < 4; r++) {
                int m = t + r * 128;
                float2 v = zz[m];
                int n0 = 2 * m, n1 = 2 * m + 1;
                float w0 = 0.5f - 0.5f * tw[n0].x;
                float w1_ = 0.5f - 0.5f * tw[n1].x;
                int g0 = foff + n0;
                int g1 = foff + n1;
                // cross-half frames overlap -> shared atomics
                if ((unsigned)g0 < (unsigned)blkLen)
                    atomicAdd(&acc[g0], v.x * (1.0f / 512.0f) * w0);
                if ((unsigned)g1 < (unsigned)blkLen)
                    atomicAdd(&acc[g1], v.y * (1.0f / 512.0f) * w1_);
            }
        }
        __syncthreads();
    }

    // ---- write block, each output element exactly once ----
    float* op = out + (size_t)b * OUTLEN + base;
    for (int i = tid; i < blkLen; i += 256) op[i] = acc[i];
}

extern "C" void kernel_launch(void* const* d_in, const int* in_sizes, int n_in,
                              void* d_out, int out_size) {
    const float* re = (const float*)d_in[0];   // stft_real [16,1024,513]
    const float* im = (const float*)d_in[1];   // stft_imag [16,1024,513]
    float* out = (float*)d_out;                // [16, 262912]
    dim3 grid(NBLK, NB);
    istft_kernel<<<grid, 256>>>(re, im, out);
}

// round 2
// speedup vs baseline: 1.7880x; 1.7880x over previous
#include <cuda_runtime.h>

#define NB       16
#define NFRAMES  1024
#define BINS     513
#define WINL     1024
#define HOP      256
#define OUTLEN   262912                  // (1024-1)*256 + 1024
#define BLK      4096                    // output samples per CTA
#define NBLK     65                      // ceil(OUTLEN / BLK)
#define NG       4                       // FFTs (frames) per CTA iteration
#define BUFSZ    576                     // padded float2 slots per FFT buffer

// smem: twF[512] float2 | bufA[NG][576] float2 | bufB[NG][576] float2 | acc[BLK] float
#define SMEM_BYTES (512*8 + 2*NG*BUFSZ*8 + BLK*4)   // 57344 = 56KB -> 4 CTAs/SM

__device__ __forceinline__ float2 cmul(float2 a, float2 b) {
    return make_float2(a.x*b.x - a.y*b.y, a.x*b.y + a.y*b.x);
}
__device__ __forceinline__ float2 cadd(float2 a, float2 b){ return make_float2(a.x+b.x, a.y+b.y); }
__device__ __forceinline__ float2 csub(float2 a, float2 b){ return make_float2(a.x-b.x, a.y-b.y); }

// padded layouts (bank-conflict-free per half-warp for this stage schedule)
__device__ __forceinline__ int P1(int e){ return e + (e >> 3); }        // max 574
__device__ __forceinline__ int P2(int e){ return e + ((e >> 6) << 3); } // max 567

// inverse radix-8 butterfly: y_k = sum_j x_j * e^{+2*pi*i*j*k/8}
__device__ __forceinline__ void bfly8_inv(const float2* x, float2* y) {
    // even set -> IDFT4
    float2 apc = cadd(x[0], x[4]), amc = csub(x[0], x[4]);
    float2 bpd = cadd(x[2], x[6]), bmd = csub(x[2], x[6]);
    float2 ib  = make_float2(-bmd.y, bmd.x);
    float2 A0 = cadd(apc, bpd), A2 = csub(apc, bpd);
    float2 A1 = cadd(amc, ib),  A3 = csub(amc, ib);
    // odd set -> IDFT4
    float2 cpc = cadd(x[1], x[5]), cmc = csub(x[1], x[5]);
    float2 dpd = cadd(x[3], x[7]), dmd = csub(x[3], x[7]);
    float2 id  = make_float2(-dmd.y, dmd.x);
    float2 B0 = cadd(cpc, dpd), B2 = csub(cpc, dpd);
    float2 B1 = cadd(cmc, id),  B3 = csub(cmc, id);
    const float r = 0.70710678118654752f;           // sqrt(2)/2
    float2 wB1  = make_float2(r*(B1.x - B1.y),  r*(B1.x + B1.y));   // w8^1 * B1
    float2 iB2  = make_float2(-B2.y, B2.x);                          // w8^2 * B2
    float2 w3B3 = make_float2(-r*(B3.x + B3.y), r*(B3.x - B3.y));   // w8^3 * B3
    y[0] = cadd(A0, B0);   y[4] = csub(A0, B0);
    y[1] = cadd(A1, wB1);  y[5] = csub(A1, wB1);
    y[2] = cadd(A2, iB2);  y[6] = csub(A2, iB2);
    y[3] = cadd(A3, w3B3); y[7] = csub(A3, w3B3);
}

__global__ void __launch_bounds__(256, 4) istft_kernel(
    const float* __restrict__ re,
    const float* __restrict__ im,
    float* __restrict__ out)
{
    extern __shared__ float smem_raw[];
    float2* twF  = (float2*)smem_raw;        // e^{+2*pi*i*k/512}, k=0..511
    float2* bufA = twF + 512;
    float2* bufB = bufA + NG * BUFSZ;
    float*  acc  = (float*)(bufB + NG * BUFSZ);

    const int tid = threadIdx.x;
    const int grp = tid >> 6;       // which FFT of the 4
    const int t   = tid & 63;       // lane within the 64-thread FFT

    const int b      = blockIdx.y;
    const int base   = blockIdx.x * BLK;
    const int blkLen = min(BLK, OUTLEN - base);

    for (int k = tid; k < 512; k += 256) {
        float s, c;
        sincospif(k * (1.0f / 256.0f), &s, &c);   // angle = 2*pi*k/512
        twF[k] = make_float2(c, s);
    }
    for (int i = tid; i < BLK; i += 256) acc[i] = 0.0f;
    __syncthreads();

    const int f_lo = max(0, (base - WINL) / HOP + 1);
    const int f_hi = min(NFRAMES - 1, (base + blkLen - 1) / HOP);

    float2* A = bufA + grp * BUFSZ;
    float2* B = bufB + grp * BUFSZ;

    for (int fp = f_lo; fp <= f_hi; fp += NG) {
        const int f = min(fp + grp, f_hi);   // clamp: redundant compute, skipped in gather

        // ---- pack: Z[k] = E[k] + i * (W_1024^k * Od[k])  (half-size complex IFFT input)
        {
            const float* rp = re + ((size_t)b * NFRAMES + f) * BINS;
            const float* ip = im + ((size_t)b * NFRAMES + f) * BINS;
            #pragma unroll
            for (int j = 0; j < 8; j++) {
                int k = t + j * 64;
                float xr = rp[k],       xi = ip[k];
                float yr = rp[512 - k], yi = ip[512 - k];
                if (k == 0) { xi = 0.0f; yi = 0.0f; }  // irfft ignores Im(DC), Im(Nyquist)
                float Er  = 0.5f * (xr + yr), Ei  = 0.5f * (xi - yi);
                float Odr = 0.5f * (xr - yr), Odi = 0.5f * (xi + yi);
                float sn, cs;
                sincospif(k * (1.0f / 512.0f), &sn, &cs);  // 2*pi*k/1024
                float Ox = Odr * cs - Odi * sn;
                float Oy = Odr * sn + Odi * cs;
                A[k] = make_float2(Er - Oy, Ei + Ox);      // linear layout
            }
        }
        __syncthreads();

        // ---- stage 0 (s=1): read A linear, write B in P1 layout ----
        {
            float2 x[8], y[8];
            #pragma unroll
            for (int j = 0; j < 8; j++) x[j] = A[t + j * 64];
            bfly8_inv(x, y);
            float2 w1 = twF[t];                 // W_512^t
            int db = 9 * t;                     // P1(8t + k) = 9t + k
            B[db] = y[0];
            float2 wk = w1;
            B[db + 1] = cmul(y[1], wk); wk = cmul(wk, w1);
            B[db + 2] = cmul(y[2], wk); wk = cmul(wk, w1);
            B[db + 3] = cmul(y[3], wk); wk = cmul(wk, w1);
            B[db + 4] = cmul(y[4], wk); wk = cmul(wk, w1);
            B[db + 5] = cmul(y[5], wk); wk = cmul(wk, w1);
            B[db + 6] = cmul(y[6], wk); wk = cmul(wk, w1);
            B[db + 7] = cmul(y[7], wk);
        }
        __syncthreads();

        // ---- stage 1 (s=8): read B (P1), write A in P2 layout ----
        {
            float2 x[8], y[8];
            #pragma unroll
            for (int j = 0; j < 8; j++) x[j] = B[P1(t + j * 64)];
            bfly8_inv(x, y);
            const int g = t >> 3, rr = t & 7;
            float2 w1 = twF[g << 3];            // W_512^{ofs}, ofs = 8g
            int db = 72 * g + rr;               // P2(64g + rr + 8k) = 72g + rr + 8k
            A[db] = y[0];
            float2 wk = w1;
            A[db +  8] = cmul(y[1], wk); wk = cmul(wk, w1);
            A[db + 16] = cmul(y[2], wk); wk = cmul(wk, w1);
            A[db + 24] = cmul(y[3], wk); wk = cmul(wk, w1);
            A[db + 32] = cmul(y[4], wk); wk = cmul(wk, w1);
            A[db + 40] = cmul(y[5], wk); wk = cmul(wk, w1);
            A[db + 48] = cmul(y[6], wk); wk = cmul(wk, w1);
            A[db + 56] = cmul(y[7], wk);
        }
        __syncthreads();

        // ---- stage 2 (s=64, ofs=0 -> twiddle = 1): read A (P2), window+scale, write B linear
        {
            float2 x[8], y[8];
            #pragma unroll
            for (int j = 0; j < 8; j++) x[j] = A[t + 72 * j];  // P2(t + 64j) = t + 72j
            bfly8_inv(x, y);
            const float CD = 0.99998117528260111f;  // cos(pi/512)
            const float SD = 0.00613588464915448f;  // sin(pi/512)
            #pragma unroll
            for (int k = 0; k < 8; k++) {
                int m = t + 64 * k;                 // z[m] holds samples 2m (re), 2m+1 (im)
                float2 w = twF[m];                  // cos/sin(pi*m/256) = cos/sin(2*pi*2m/1024)
                float w0 = (0.5f - 0.5f * w.x) * (1.0f / 512.0f);
                float c1 = w.x * CD - w.y * SD;     // cos(2*pi*(2m+1)/1024)
                float w1w = (0.5f - 0.5f * c1) * (1.0f / 512.0f);
                B[m] = make_float2(y[k].x * w0, y[k].y * w1w);
            }
        }
        __syncthreads();

        // ---- gather overlap-add: each output sample owned by one thread, no atomics
        {
            const int fc_hi = min(fp + NG - 1, f_hi);
            const int nact  = fc_hi - fp;                       // active groups c <= nact
            const int i0 = max(0, fp * HOP - base);
            const int i1 = min(blkLen, fc_hi * HOP + WINL - base);
            const int d0 = base - fp * HOP;
            for (int i = i0 + tid; i < i1; i += 256) {
                int d = i + d0;
                float v = acc[i];
                #pragma unroll
                for (int c = 0; c < NG; c++) {
                    int n = d - c * HOP;
                    if (c <= nact && (unsigned)n < (unsigned)WINL)
                        v += ((const float*)(bufB + c * BUFSZ))[n];
                }
                acc[i] = v;
            }
        }
        __syncthreads();
    }

    float* op = out + (size_t)b * OUTLEN + base;
    for (int i = tid; i < blkLen; i += 256) op[i] = acc[i];
}

extern "C" void kernel_launch(void* const* d_in, const int* in_sizes, int n_in,
                              void* d_out, int out_size) {
    const float* re = (const float*)d_in[0];   // stft_real [16,1024,513]
    const float* im = (const float*)d_in[1];   // stft_imag [16,1024,513]
    float* out = (float*)d_out;                // [16, 262912]
    cudaFuncSetAttribute(istft_kernel, cudaFuncAttributeMaxDynamicSharedMemorySize, SMEM_BYTES);
    dim3 grid(NBLK, NB);
    istft_kernel<<<grid, 256, SMEM_BYTES>>>(re, im, out);
}

// round 3
// speedup vs baseline: 2.1119x; 1.1811x over previous
#include <cuda_runtime.h>

#define NB       16
#define NFRAMES  1024
#define BINS     513
#define WINL     1024
#define HOP      256
#define OUTLEN   262912                  // (1024-1)*256 + 1024
#define BLK      4096                    // output samples per CTA
#define NBLK     65                      // ceil(OUTLEN / BLK)
#define NG       4                       // FFTs (frames) per CTA iteration
#define BUFSZ    576                     // padded float2 slots per FFT buffer

// smem: twF[512] float2 | buf[NG][576] float2 | acc[BLK] float = 4K + 18K + 16K = 38KB
#define SMEM_BYTES (512*8 + NG*BUFSZ*8 + BLK*4)

__device__ __forceinline__ float2 cmul(float2 a, float2 b) {
    return make_float2(a.x*b.x - a.y*b.y, a.x*b.y + a.y*b.x);
}
__device__ __forceinline__ float2 cadd(float2 a, float2 b){ return make_float2(a.x+b.x, a.y+b.y); }
__device__ __forceinline__ float2 csub(float2 a, float2 b){ return make_float2(a.x-b.x, a.y-b.y); }

// padded layouts (bank-conflict-free for this stage schedule)
__device__ __forceinline__ int P1(int e){ return e + (e >> 3); }        // max 574 < 576
__device__ __forceinline__ int P2(int e){ return e + ((e >> 6) << 3); } // max 567 < 576

// inverse radix-8 butterfly: y_k = sum_j x_j * e^{+2*pi*i*j*k/8}
__device__ __forceinline__ void bfly8_inv(const float2* x, float2* y) {
    float2 apc = cadd(x[0], x[4]), amc = csub(x[0], x[4]);
    float2 bpd = cadd(x[2], x[6]), bmd = csub(x[2], x[6]);
    float2 ib  = make_float2(-bmd.y, bmd.x);
    float2 A0 = cadd(apc, bpd), A2 = csub(apc, bpd);
    float2 A1 = cadd(amc, ib),  A3 = csub(amc, ib);
    float2 cpc = cadd(x[1], x[5]), cmc = csub(x[1], x[5]);
    float2 dpd = cadd(x[3], x[7]), dmd = csub(x[3], x[7]);
    float2 id  = make_float2(-dmd.y, dmd.x);
    float2 B0 = cadd(cpc, dpd), B2 = csub(cpc, dpd);
    float2 B1 = cadd(cmc, id),  B3 = csub(cmc, id);
    const float r = 0.70710678118654752f;
    float2 wB1  = make_float2(r*(B1.x - B1.y),  r*(B1.x + B1.y));   // w8^1 * B1
    float2 iB2  = make_float2(-B2.y, B2.x);                          // w8^2 * B2
    float2 w3B3 = make_float2(-r*(B3.x + B3.y), r*(B3.x - B3.y));   // w8^3 * B3
    y[0] = cadd(A0, B0);   y[4] = csub(A0, B0);
    y[1] = cadd(A1, wB1);  y[5] = csub(A1, wB1);
    y[2] = cadd(A2, iB2);  y[6] = csub(A2, iB2);
    y[3] = cadd(A3, w3B3); y[7] = csub(A3, w3B3);
}

__global__ void __launch_bounds__(256, 4) istft_kernel(
    const float* __restrict__ re,
    const float* __restrict__ im,
    float* __restrict__ out)
{
    extern __shared__ float smem_raw[];
    float2* twF = (float2*)smem_raw;         // e^{+2*pi*i*k/512}, k=0..511
    float2* buf = twF + 512;                 // NG buffers of BUFSZ float2
    float*  acc = (float*)(buf + NG * BUFSZ);

    const int tid = threadIdx.x;
    const int grp = tid >> 6;       // which FFT of the 4
    const int t   = tid & 63;       // lane within the 64-thread FFT

    const int b      = blockIdx.y;
    const int base   = blockIdx.x * BLK;
    const int blkLen = min(BLK, OUTLEN - base);

    for (int k = tid; k < 512; k += 256) {
        float s, c;
        sincospif(k * (1.0f / 256.0f), &s, &c);   // angle = 2*pi*k/512
        twF[k] = make_float2(c, s);
    }
    for (int i = tid; i < BLK; i += 256) acc[i] = 0.0f;
    __syncthreads();

    const int f_lo = max(0, (base - WINL) / HOP + 1);
    const int f_hi = min(NFRAMES - 1, (base + blkLen - 1) / HOP);

    float2* B = buf + grp * BUFSZ;

    // pack twiddle step: e^{+i*pi/8} (advance k by 64 in W_1024^k)
    const float STC = 0.92387953251128676f;   // cos(pi/8)
    const float STS = 0.38268343236508977f;   // sin(pi/8)

    for (int fp = f_lo; fp <= f_hi; fp += NG) {
        const int f = min(fp + grp, f_hi);   // clamp: redundant compute, skipped in gather

        // ---- fused pack + stage 0 (s=1), entirely in registers ----
        {
            const float* rp = re + ((size_t)b * NFRAMES + f) * BINS;
            const float* ip = im + ((size_t)b * NFRAMES + f) * BINS;
            float sn, cs;
            sincospif(t * (1.0f / 512.0f), &sn, &cs);  // W_1024^t
            float2 wp = make_float2(cs, sn);
            float2 x[8], y[8];
            #pragma unroll
            for (int j = 0; j < 8; j++) {
                int k = t + j * 64;
                float xr = rp[k],       xi = ip[k];
                float yr = rp[512 - k], yi = ip[512 - k];
                if (k == 0) { xi = 0.0f; yi = 0.0f; }  // irfft ignores Im(DC), Im(Nyquist)
                float Er  = 0.5f * (xr + yr), Ei  = 0.5f * (xi - yi);
                float Odr = 0.5f * (xr - yr), Odi = 0.5f * (xi + yi);
                float Ox = Odr * wp.x - Odi * wp.y;
                float Oy = Odr * wp.y + Odi * wp.x;
                x[j] = make_float2(Er - Oy, Ei + Ox);
                wp = make_float2(wp.x * STC - wp.y * STS, wp.x * STS + wp.y * STC);
            }
            bfly8_inv(x, y);
            float2 w1 = twF[t];                 // W_512^t
            int db = 9 * t;                     // P1(8t + k) = 9t + k
            B[db] = y[0];
            float2 wk = w1;
            B[db + 1] = cmul(y[1], wk); wk = cmul(wk, w1);
            B[db + 2] = cmul(y[2], wk); wk = cmul(wk, w1);
            B[db + 3] = cmul(y[3], wk); wk = cmul(wk, w1);
            B[db + 4] = cmul(y[4], wk); wk = cmul(wk, w1);
            B[db + 5] = cmul(y[5], wk); wk = cmul(wk, w1);
            B[db + 6] = cmul(y[6], wk); wk = cmul(wk, w1);
            B[db + 7] = cmul(y[7], wk);
        }
        __syncthreads();

        // ---- stage 1 (s=8): in-place, read P1 -> sync -> write P2 ----
        {
            float2 x[8], y[8];
            #pragma unroll
            for (int j = 0; j < 8; j++) x[j] = B[P1(t + j * 64)];
            bfly8_inv(x, y);
            __syncthreads();
            const int g = t >> 3, rr = t & 7;
            float2 w1 = twF[g << 3];            // W_512^{8g}
            int db = 72 * g + rr;               // P2(64g + rr + 8k) = 72g + rr + 8k
            B[db] = y[0];
            float2 wk = w1;
            B[db +  8] = cmul(y[1], wk); wk = cmul(wk, w1);
            B[db + 16] = cmul(y[2], wk); wk = cmul(wk, w1);
            B[db + 24] = cmul(y[3], wk); wk = cmul(wk, w1);
            B[db + 32] = cmul(y[4], wk); wk = cmul(wk, w1);
            B[db + 40] = cmul(y[5], wk); wk = cmul(wk, w1);
            B[db + 48] = cmul(y[6], wk); wk = cmul(wk, w1);
            B[db + 56] = cmul(y[7], wk);
        }
        __syncthreads();

        // ---- stage 2 (s=64, twiddle=1): in-place, read P2 -> sync -> windowed linear write
        {
            float2 x[8], y[8];
            #pragma unroll
            for (int j = 0; j < 8; j++) x[j] = B[t + 72 * j];  // P2(t + 64j)
            bfly8_inv(x, y);
            __syncthreads();
            const float CD = 0.99998117528260111f;  // cos(pi/512)
            const float SD = 0.00613588464915448f;  // sin(pi/512)
            #pragma unroll
            for (int k = 0; k < 8; k++) {
                int m = t + 64 * k;                 // z[m] = samples 2m (re), 2m+1 (im)
                float2 w = twF[m];                  // cos/sin(2*pi*2m/1024)
                float w0 = (0.5f - 0.5f * w.x) * (1.0f / 512.0f);
                float c1 = w.x * CD - w.y * SD;     // cos(2*pi*(2m+1)/1024)
                float w1w = (0.5f - 0.5f * c1) * (1.0f / 512.0f);
                B[m] = make_float2(y[k].x * w0, y[k].y * w1w);
            }
        }
        __syncthreads();

        // ---- gather overlap-add: compile-time (r,c) schedule, uniform guards only ----
        {
            const int nact = min(fp + NG - 1, f_hi) - fp;      // active groups c <= nact
            const int q    = (base - fp * HOP) / HOP;          // exact (multiples of 256)
            const int rhi  = q + (blkLen >> 8) - 1;
            const float* bf = (const float*)buf;               // group c stride = 1152 floats
            #pragma unroll
            for (int r = 0; r < 7; r++) {
                if (r < q || r > rhi) continue;                // CTA-uniform
                const int i = tid + ((r - q) << 8);
                float v = acc[i];
                #pragma unroll
                for (int c = 0; c < NG; c++) {
                    if (c > r || c < r - 3) continue;          // compile-time
                    if (c <= nact)                             // CTA-uniform
                        v += bf[c * (2 * BUFSZ) + tid + ((r - c) << 8)];
                }
                acc[i] = v;
            }
        }
        __syncthreads();
    }

    float* op = out + (size_t)b * OUTLEN + base;
    for (int i = tid; i < blkLen; i += 256) op[i] = acc[i];
}

extern "C" void kernel_launch(void* const* d_in, const int* in_sizes, int n_in,
                              void* d_out, int out_size) {
    const float* re = (const float*)d_in[0];   // stft_real [16,1024,513]
    const float* im = (const float*)d_in[1];   // stft_imag [16,1024,513]
    float* out = (float*)d_out;                // [16, 262912]
    cudaFuncSetAttribute(istft_kernel, cudaFuncAttributeMaxDynamicSharedMemorySize, SMEM_BYTES);
    dim3 grid(NBLK, NB);
    istft_kernel<<<grid, 256, SMEM_BYTES>>>(re, im, out);
}